// round 2
// baseline (speedup 1.0000x reference)
#include <cuda_runtime.h>

// Problem constants (fixed by the dataset)
#define BSZ 8
#define QN  500
#define TN  400
#define PN  (BSZ*QN)     // 4000 flattened preds
#define NBLOCKS 152      // one persistent block per GB300 SM
#define TPB 416          // 13 warps; threads [0,400) own one target each
#define MAXPPB 28        // >= ceil(PN/NBLOCKS)+1

typedef unsigned long long ull;

// ---- packed f32x2 helpers (sm_103a double-rate fp32) ----
__device__ __forceinline__ ull pk2(float lo, float hi) {
    ull r; asm("mov.b64 %0, {%1,%2};" : "=l"(r) : "f"(lo), "f"(hi)); return r;
}
__device__ __forceinline__ void upk2(ull v, float& lo, float& hi) {
    asm("mov.b64 {%0,%1}, %2;" : "=f"(lo), "=f"(hi) : "l"(v));
}
__device__ __forceinline__ ull padd2(ull a, ull b) {
    ull r; asm("add.rn.f32x2 %0, %1, %2;" : "=l"(r) : "l"(a), "l"(b)); return r;
}
__device__ __forceinline__ ull pfma2(ull a, ull b, ull c) {
    ull r; asm("fma.rn.f32x2 %0, %1, %2, %3;" : "=l"(r) : "l"(a), "l"(b), "l"(c)); return r;
}

#define NINE2  0x4110000041100000ULL   // {9.0f, 9.0f}
#define SEVEN2 0x40E0000040E00000ULL   // {7.0f, 7.0f}

__global__ __launch_bounds__(TPB, 1)
void matcher_kernel(const float* __restrict__ logits,   // [PN,2]
                    const float* __restrict__ pkp,      // [PN,53]
                    const int*   __restrict__ tids,     // [TN]
                    const float* __restrict__ tkp,      // [TN,53]
                    const int*   __restrict__ nbp,      // scalar num_boxes
                    float*       __restrict__ out)      // [PN,TN]
{
    // Per-pred block of 64 floats in shared:
    //   [ 0..33] Zp (keypoint deltas), [34..35] zero pad
    //   [36..59] dot vector: Vp[17], Cp0, Cp1, (p0-p1), 1.0, s_p-p0, 0, 0
    //   [60..61] Cp0, Cp1          [62..63] pad
    __shared__ __align__(16) float smP[MAXPPB * 64];

    const int b = blockIdx.x;
    const int pbase = (b * PN) / NBLOCKS;
    const int npred = ((b + 1) * PN) / NBLOCKS - pbase;
    const int tid = threadIdx.x;

    int nbi = *nbp;
    float nb = (nbi > 0 && nbi < (1 << 20)) ? (float)nbi : *(const float*)nbp;
    const float inb = 1.0f / nb;

    // ---- pred preprocessing into shared (one thread per pred, once) ----
    if (tid < npred) {
        const int gp = pbase + tid;
        const float l0 = logits[gp * 2 + 0];
        const float l1 = logits[gp * 2 + 1];
        const float m  = fmaxf(l0, l1);
        const float e0 = __expf(l0 - m);
        const float e1 = __expf(l1 - m);
        const float inv = 1.0f / (e0 + e1);
        const float p0 = e0 * inv, p1 = e1 * inv;

        const float* kp = pkp + gp * 53;
        const float c0 = kp[0], c1 = kp[1];
        float* sp = smP + tid * 64;
        #pragma unroll
        for (int k = 0; k < 34; ++k) sp[k] = kp[2 + k];   // Zp
        sp[34] = 0.0f; sp[35] = 0.0f;
        float sv = 0.0f;
        #pragma unroll
        for (int j = 0; j < 17; ++j) {
            float v = kp[36 + j];
            sp[36 + j] = v;                                // Vp
            sv = fmaf(v, v, sv);
        }
        sp[53] = c0;
        sp[54] = c1;
        sp[55] = p0 - p1;
        sp[56] = 1.0f;
        sp[57] = 0.2f * inb * sv + 0.5f * inb * (c0 * c0 + c1 * c1) - p0;
        sp[58] = 0.0f;
        sp[59] = 0.0f;
        sp[60] = c0;
        sp[61] = c1;
        sp[62] = 0.0f;
        sp[63] = 0.0f;
    }
    __syncthreads();

    // ---- target features into REGISTERS (lane = target) ----
    const int  t = tid;
    const bool active = (t < TN);
    ull   nzg[18];     // packed {-Zg[2j], -Zg[2j+1]}
    float w[18];       // 0.5*Vg/nb per keypoint (shared by x,y)
    ull   td2[12];     // packed dot coefficients (24 scalars)
    float ng8x, ng8y;  // -8*Cg
    if (active) {
        const float* tk = tkp + t * 53;
        const float c0 = tk[0], c1 = tk[1];
        #pragma unroll
        for (int j = 0; j < 17; ++j)
            nzg[j] = pk2(-tk[2 + 2 * j], -tk[3 + 2 * j]);
        nzg[17] = 0ULL;
        float sv = 0.0f;
        float tdv[24];
        #pragma unroll
        for (int j = 0; j < 17; ++j) {
            float v = tk[36 + j];
            w[j]   = 0.5f * inb * v;
            tdv[j] = -0.4f * inb * v;
            sv = fmaf(v, v, sv);
        }
        w[17] = 0.0f;
        tdv[17] = -inb * c0;
        tdv[18] = -inb * c1;
        tdv[19] = (float)tids[t];
        tdv[20] = 0.2f * inb * sv + 0.5f * inb * (c0 * c0 + c1 * c1);
        tdv[21] = 1.0f;
        tdv[22] = 0.0f;
        tdv[23] = 0.0f;
        #pragma unroll
        for (int j = 0; j < 12; ++j) td2[j] = pk2(tdv[2 * j], tdv[2 * j + 1]);
        ng8x = -8.0f * c0;
        ng8y = -8.0f * c1;
    } else {
        #pragma unroll
        for (int j = 0; j < 18; ++j) { nzg[j] = 0ULL; w[j] = 0.0f; }
        #pragma unroll
        for (int j = 0; j < 12; ++j) td2[j] = 0ULL;
        ng8x = 0.0f; ng8y = 0.0f;
    }

    // ---- main loop over preds: broadcast LDS, all math in registers ----
    for (int p = 0; p < npred; ++p) {
        const float* pp = smP + p * 64;
        const float cp0 = pp[60], cp1 = pp[61];
        // packed 8*(Cp - Cg) — same for every keypoint of this (pred,target)
        const ull h8 = pk2(fmaf(cp0, 8.0f, ng8x), fmaf(cp1, 8.0f, ng8y));

        float s0 = 0.0f, s1 = 0.0f, s2 = 0.0f, s3 = 0.0f;
        const ulonglong2* zp = (const ulonglong2*)pp;     // 36 Zp floats = 9 x 16B
        #pragma unroll
        for (int q = 0; q < 9; ++q) {
            ulonglong2 zz = zp[q];                        // broadcast LDS.128
            {   // pair 2q : keypoints 4q, 4q+1
                ull dz = padd2(zz.x, nzg[2 * q]);
                ull u1 = pfma2(dz, NINE2,  h8);
                ull u2 = pfma2(dz, SEVEN2, h8);
                float a0, a1, b0, b1;
                upk2(u1, a0, a1); upk2(u2, b0, b1);
                float wj = w[2 * q];
                s0 = fmaf(fmaxf(fabsf(a0), fabsf(b0)), wj, s0);
                s1 = fmaf(fmaxf(fabsf(a1), fabsf(b1)), wj, s1);
            }
            {   // pair 2q+1 : keypoints 4q+2, 4q+3
                ull dz = padd2(zz.y, nzg[2 * q + 1]);
                ull u1 = pfma2(dz, NINE2,  h8);
                ull u2 = pfma2(dz, SEVEN2, h8);
                float a0, a1, b0, b1;
                upk2(u1, a0, a1); upk2(u2, b0, b1);
                float wj = w[2 * q + 1];
                s2 = fmaf(fmaxf(fabsf(a0), fabsf(b0)), wj, s2);
                s3 = fmaf(fmaxf(fabsf(a1), fabsf(b1)), wj, s3);
            }
        }

        // quadratic + class terms as a packed 24-dim dot product
        ull d0 = 0ULL, d1 = 0ULL;
        const ulonglong2* pd = (const ulonglong2*)(pp + 36);
        #pragma unroll
        for (int q = 0; q < 6; ++q) {
            ulonglong2 v = pd[q];                          // broadcast LDS.128
            d0 = pfma2(v.x, td2[2 * q],     d0);
            d1 = pfma2(v.y, td2[2 * q + 1], d1);
        }
        float d0l, d0h, d1l, d1h;
        upk2(d0, d0l, d0h); upk2(d1, d1l, d1h);

        if (active)
            out[(size_t)(pbase + p) * TN + t] =
                ((s0 + s1) + (s2 + s3)) + ((d0l + d0h) + (d1l + d1h));
    }
}

extern "C" void kernel_launch(void* const* d_in, const int* in_sizes, int n_in,
                              void* d_out, int out_size)
{
    const float* logits = (const float*)d_in[0];   // pred_logits   [8,500,2]
    const float* pkp    = (const float*)d_in[1];   // pred_keypoints[8,500,53]
    const int*   tids   = (const int*)  d_in[2];   // tgt_ids       [400]
    const float* tkp    = (const float*)d_in[3];   // tgt_keypoints [400,53]
    const int*   nbp    = (const int*)  d_in[4];   // num_boxes scalar
    (void)in_sizes; (void)n_in; (void)out_size;

    matcher_kernel<<<NBLOCKS, TPB>>>(logits, pkp, tids, tkp, nbp, (float*)d_out);
}

// round 3
// speedup vs baseline: 1.0013x; 1.0013x over previous
#include <cuda_runtime.h>

#define BSZ 8
#define QN  500
#define TN  400
#define PN  (BSZ*QN)      // 4000 flattened preds
#define NBLOCKS 152       // one block per GB300 SM
#define TPB 832           // two warp-groups of 416 threads (26 warps)
#define GW  416
#define MAXP 28           // >= ceil(PN/NBLOCKS)+1

typedef unsigned long long ull;

// ---- packed f32x2 helpers (sm_103a double-rate fp32) ----
__device__ __forceinline__ ull pk2(float lo, float hi) {
    ull r; asm("mov.b64 %0, {%1,%2};" : "=l"(r) : "f"(lo), "f"(hi)); return r;
}
__device__ __forceinline__ float2 u2f2(ull v) {
    float2 f; asm("mov.b64 {%0,%1}, %2;" : "=f"(f.x), "=f"(f.y) : "l"(v)); return f;
}
__device__ __forceinline__ ull padd2(ull a, ull b) {
    ull r; asm("add.rn.f32x2 %0, %1, %2;" : "=l"(r) : "l"(a), "l"(b)); return r;
}
__device__ __forceinline__ ull pfma2(ull a, ull b, ull c) {
    ull r; asm("fma.rn.f32x2 %0, %1, %2, %3;" : "=l"(r) : "l"(a), "l"(b), "l"(c)); return r;
}

#define NINE2  0x4110000041100000ULL   // {9.0f, 9.0f}
#define SEVEN2 0x40E0000040E00000ULL   // {7.0f, 7.0f}

// dynamic shared layout:
//   [0)                ull  zgn[17*400]   negated target keypoint pairs, lane-major
//   [17*400*8)         float ptile[MAXP*64] preprocessed pred rows
#define ZGN_WORDS (17*400)
#define SMEM_BYTES (ZGN_WORDS*8 + MAXP*64*4)

__global__ __launch_bounds__(TPB, 1)
void matcher_kernel(const float* __restrict__ logits,   // [PN,2]
                    const float* __restrict__ pkp,      // [PN,53]
                    const int*   __restrict__ tids,     // [TN]
                    const float* __restrict__ tkp,      // [TN,53]
                    const int*   __restrict__ nbp,      // scalar num_boxes
                    float*       __restrict__ out)      // [PN,TN]
{
    extern __shared__ __align__(16) char dsm[];
    ull*   zgn   = (ull*)dsm;
    float* ptile = (float*)(dsm + ZGN_WORDS * 8);

    const int b = blockIdx.x;
    const int pbase = (b * PN) / NBLOCKS;
    const int npred = ((b + 1) * PN) / NBLOCKS - pbase;
    const int tid = threadIdx.x;
    const int g = tid / GW;           // warp-group 0/1
    const int t = tid - g * GW;       // target lane within group
    const bool active = (t < TN);
    const int tt = active ? t : 0;    // safe shared index for inactive lanes

    int nbi = *nbp;
    float nb = (nbi > 0 && nbi < (1 << 20)) ? (float)nbi : *(const float*)nbp;
    const float inb = 1.0f / nb;

    // ---- pred preprocessing into shared (threads 0..npred-1, once) ----
    if (tid < npred) {
        const int gp = pbase + tid;
        const float l0 = logits[gp * 2 + 0];
        const float l1 = logits[gp * 2 + 1];
        const float m  = fmaxf(l0, l1);
        const float e0 = __expf(l0 - m);
        const float e1 = __expf(l1 - m);
        const float inv = 1.0f / (e0 + e1);
        const float p0 = e0 * inv, p1 = e1 * inv;

        const float* kp = pkp + gp * 53;
        const float c0 = kp[0], c1 = kp[1];
        float* sp = ptile + tid * 64;
        #pragma unroll
        for (int k = 0; k < 34; ++k) sp[k] = kp[2 + k];      // Zp
        float sv = 0.0f;
        #pragma unroll
        for (int j = 0; j < 17; ++j) {
            float v = kp[36 + j];
            sp[36 + j] = v;                                   // Vp
            sv = fmaf(v, v, sv);
        }
        sp[53] = c0;
        sp[54] = c1;
        sp[55] = p0 - p1;                                     // class delta
        sp[56] = 0.2f * inb * sv + 0.5f * inb * (c0 * c0 + c1 * c1) - p0;  // spp
    }

    // ---- target Zg tile into shared (group 0 only; negated, packed) ----
    if (g == 0 && active) {
        const float* tk = tkp + t * 53;
        #pragma unroll
        for (int j = 0; j < 17; ++j)
            zgn[j * TN + t] = pk2(-tk[2 + 2 * j], -tk[3 + 2 * j]);
    }

    // ---- per-target register state (both groups) ----
    float w[17];
    float ng8x = 0.0f, ng8y = 0.0f, tcx = 0.0f, tcy = 0.0f, idf = 0.0f, sgt = 0.0f;
    if (active) {
        const float* tk = tkp + t * 53;
        const float c0 = tk[0], c1 = tk[1];
        float sv = 0.0f;
        #pragma unroll
        for (int j = 0; j < 17; ++j) {
            float v = tk[36 + j];
            w[j] = 0.5f * inb * v;
            sv = fmaf(v, v, sv);
        }
        ng8x = -8.0f * c0;
        ng8y = -8.0f * c1;
        tcx  = -inb * c0;
        tcy  = -inb * c1;
        idf  = (float)tids[t];
        sgt  = 0.2f * inb * sv + 0.5f * inb * (c0 * c0 + c1 * c1);
    } else {
        #pragma unroll
        for (int j = 0; j < 17; ++j) w[j] = 0.0f;
    }
    __syncthreads();

    // ---- pred range for this warp-group ----
    const int nh = (npred + 1) >> 1;
    const int pLo = g ? nh : 0;
    const int pHi = g ? npred : nh;

    for (int p = pLo; p < pHi; ++p) {
        const float* pp = ptile + p * 64;

        // tail vector: {Vp[16], cp0, cp1, p0-p1}
        const float4 v4 = *(const float4*)(pp + 52);
        const ull hp = pk2(fmaf(v4.y, 8.0f, ng8x), fmaf(v4.z, 8.0f, ng8y));

        float s0 = 0.0f, s1 = 0.0f, s2 = 0.0f, s3 = 0.0f;
        const ulonglong2* zp = (const ulonglong2*)pp;
        #pragma unroll
        for (int q = 0; q < 8; ++q) {
            ulonglong2 z = zp[q];                       // broadcast LDS.128 (kp 4q..4q+3)
            ull za = zgn[(2 * q) * TN + tt];            // per-lane LDS.64
            ull zb = zgn[(2 * q + 1) * TN + tt];
            {
                ull dz = padd2(z.x, za);
                ull u1 = pfma2(dz, NINE2,  hp);
                ull u2 = pfma2(dz, SEVEN2, hp);
                float2 a = u2f2(u1), c = u2f2(u2);
                float wq = w[2 * q];
                s0 = fmaf(fmaxf(fabsf(a.x), fabsf(c.x)), wq, s0);
                s1 = fmaf(fmaxf(fabsf(a.y), fabsf(c.y)), wq, s1);
            }
            {
                ull dz = padd2(z.y, zb);
                ull u1 = pfma2(dz, NINE2,  hp);
                ull u2 = pfma2(dz, SEVEN2, hp);
                float2 a = u2f2(u1), c = u2f2(u2);
                float wq = w[2 * q + 1];
                s2 = fmaf(fmaxf(fabsf(a.x), fabsf(c.x)), wq, s2);
                s3 = fmaf(fmaxf(fabsf(a.y), fabsf(c.y)), wq, s3);
            }
        }
        {   // final keypoint pair (kp 32,33)
            ull z16 = *(const ull*)(pp + 32);
            ull zc  = zgn[16 * TN + tt];
            ull dz = padd2(z16, zc);
            ull u1 = pfma2(dz, NINE2,  hp);
            ull u2 = pfma2(dz, SEVEN2, hp);
            float2 a = u2f2(u1), c = u2f2(u2);
            float wq = w[16];
            s0 = fmaf(fmaxf(fabsf(a.x), fabsf(c.x)), wq, s0);
            s1 = fmaf(fmaxf(fabsf(a.y), fabsf(c.y)), wq, s1);
        }

        // viz cross term: dv = sum Vp[j]*w[j]; contributes -0.8*dv
        const float4 q0 = *(const float4*)(pp + 36);
        const float4 q1 = *(const float4*)(pp + 40);
        const float4 q2 = *(const float4*)(pp + 44);
        const float4 q3 = *(const float4*)(pp + 48);
        float dv = q0.x * w[0];
        dv = fmaf(q0.y, w[1],  dv); dv = fmaf(q0.z, w[2],  dv); dv = fmaf(q0.w, w[3],  dv);
        dv = fmaf(q1.x, w[4],  dv); dv = fmaf(q1.y, w[5],  dv); dv = fmaf(q1.z, w[6],  dv);
        dv = fmaf(q1.w, w[7],  dv); dv = fmaf(q2.x, w[8],  dv); dv = fmaf(q2.y, w[9],  dv);
        dv = fmaf(q2.z, w[10], dv); dv = fmaf(q2.w, w[11], dv); dv = fmaf(q3.x, w[12], dv);
        dv = fmaf(q3.y, w[13], dv); dv = fmaf(q3.z, w[14], dv); dv = fmaf(q3.w, w[15], dv);
        dv = fmaf(v4.x, w[16], dv);

        float res = (s0 + s1) + (s2 + s3);
        res = fmaf(dv, -0.8f, res);
        res = fmaf(v4.y, tcx, res);     // center cross x
        res = fmaf(v4.z, tcy, res);     // center cross y
        res = fmaf(v4.w, idf, res);     // class: id*(p0-p1)
        res += sgt + pp[56];            // target const + pred const (incl. -p0)

        if (active)
            out[(size_t)(pbase + p) * TN + t] = res;
    }
}

extern "C" void kernel_launch(void* const* d_in, const int* in_sizes, int n_in,
                              void* d_out, int out_size)
{
    const float* logits = (const float*)d_in[0];   // pred_logits   [8,500,2]
    const float* pkp    = (const float*)d_in[1];   // pred_keypoints[8,500,53]
    const int*   tids   = (const int*)  d_in[2];   // tgt_ids       [400]
    const float* tkp    = (const float*)d_in[3];   // tgt_keypoints [400,53]
    const int*   nbp    = (const int*)  d_in[4];   // num_boxes scalar
    (void)in_sizes; (void)n_in; (void)out_size;

    cudaFuncSetAttribute(matcher_kernel,
                         cudaFuncAttributeMaxDynamicSharedMemorySize, SMEM_BYTES);
    matcher_kernel<<<NBLOCKS, TPB, SMEM_BYTES>>>(logits, pkp, tids, tkp, nbp,
                                                 (float*)d_out);
}